// round 4
// baseline (speedup 1.0000x reference)
#include <cuda_runtime.h>

// Problem constants
#define N_ROWS 65536   // B*H*W = 64*32*32
#define DIM    256     // D
#define KCB    1024    // K

#define OFF_PERP  16777216
#define OFF_LOSS  16777217
#define OFF_CB    16777218

// ---------------- scratch (device globals; no allocation allowed) -----------
__device__ float g_cbT[KCB * DIM];      // codebook transposed [K, D]
__device__ float g_cnorm[KCB];          // |e_k|^2
__device__ float g_xnorm[N_ROWS];       // |x_n|^2
__device__ float g_pminval[N_ROWS * 8]; // per-(row, ktile) partial min value
__device__ int   g_pminidx[N_ROWS * 8]; // per-(row, ktile) partial argmin
__device__ int   g_idx[N_ROWS];         // final argmin index per row
__device__ float g_counts[KCB];         // cluster sizes (float, like one-hot sum)
__device__ float g_dwT[KCB * DIM];      // dw transposed [K, D]
__device__ float g_loss_sum;            // sum of (q-x)^2
__device__ float g_smoothed[KCB];       // smoothed cluster size
__device__ float g_bias;                // 1 - gamma^counter

// ---------------- kernels ---------------------------------------------------

// Zero the accumulators that the scatter pass updates (graph replays!).
__global__ void k_zero() {
    int i = blockIdx.x * 256 + threadIdx.x;   // grid 1024 -> covers KCB*DIM
    if (i < KCB * DIM) g_dwT[i] = 0.0f;
    if (i < KCB)       g_counts[i] = 0.0f;
    if (i == 0)        g_loss_sum = 0.0f;
}

// Transpose codebook [D,K] -> cbT [K,D] (coalesced both sides via smem tile).
__global__ void k_transpose(const float* __restrict__ cb) {
    __shared__ float tile[32][33];
    int k0 = blockIdx.x * 32;
    int d0 = blockIdx.y * 32;
    int x = threadIdx.x, y = threadIdx.y;
    tile[y][x] = cb[(d0 + y) * KCB + (k0 + x)];
    __syncthreads();
    g_cbT[(k0 + y) * DIM + (d0 + x)] = tile[x][y];
}

// Per-code squared norm from cbT (contiguous rows). 1024 blocks x 32 threads.
__global__ void k_cnorm() {
    int k = blockIdx.x, lane = threadIdx.x;
    float s = 0.0f;
#pragma unroll
    for (int i = 0; i < 8; i++) {
        float v = g_cbT[k * DIM + lane + 32 * i];
        s = fmaf(v, v, s);
    }
#pragma unroll
    for (int o = 16; o; o >>= 1) s += __shfl_xor_sync(0xffffffffu, s, o);
    if (lane == 0) g_cnorm[k] = s;
}

// Per-row squared norm. 8192 blocks x 256 threads, one warp per row.
__global__ void k_xnorm(const float* __restrict__ x) {
    int warp = threadIdx.x >> 5, lane = threadIdx.x & 31;
    int r = blockIdx.x * 8 + warp;
    const float* xr = x + (size_t)r * DIM;
    float s = 0.0f;
#pragma unroll
    for (int i = 0; i < 8; i++) {
        float v = xr[lane + 32 * i];
        s = fmaf(v, v, s);
    }
#pragma unroll
    for (int o = 16; o; o >>= 1) s += __shfl_xor_sync(0xffffffffu, s, o);
    if (lane == 0) g_xnorm[r] = s;
}

// Fused SGEMM + per-row partial argmin.
// Block tile: 128 rows x 128 codes, full D=256 accumulation (32 stages of 8).
// Thread microtile 8x8. Double-buffered smem, one __syncthreads per stage.
__global__ __launch_bounds__(256, 2) void k_gemm_argmin(
    const float* __restrict__ A,   // flat [N, 256]
    const float* __restrict__ B)   // codebook [256, 1024]
{
    __shared__ __align__(16) float As[2][8][132];  // [buf][d][row]
    __shared__ __align__(16) float Bs[2][8][132];  // [buf][d][col]
    __shared__ float redv[128][17];
    __shared__ int   redi[128][17];

    const int r0 = blockIdx.x * 128;
    const int c0 = blockIdx.y * 128;
    const int t  = threadIdx.x;
    const int tx = t & 15, ty = t >> 4;

    // global load mapping
    const int arow  = t >> 1;            // 0..127
    const int acol4 = (t & 1) * 4;       // 0 or 4
    const int brow  = t >> 5;            // 0..7
    const int bcol  = (t & 31) * 4;      // 0..124

    const float* aptr = A + (size_t)(r0 + arow) * DIM + acol4;
    const float* bptr = B + (size_t)brow * KCB + c0 + bcol;

    // stage 0 load
    {
        float4 av = *(const float4*)aptr;
        float4 bv = *(const float4*)bptr;
        As[0][acol4 + 0][arow] = av.x;
        As[0][acol4 + 1][arow] = av.y;
        As[0][acol4 + 2][arow] = av.z;
        As[0][acol4 + 3][arow] = av.w;
        *(float4*)&Bs[0][brow][bcol] = bv;
    }
    __syncthreads();

    float acc[8][8];
#pragma unroll
    for (int i = 0; i < 8; i++)
#pragma unroll
        for (int j = 0; j < 8; j++) acc[i][j] = 0.0f;

#pragma unroll 1
    for (int s = 0; s < 32; s++) {
        const int cur = s & 1;
        float4 av, bv;
        if (s < 31) {
            av = *(const float4*)(aptr + (s + 1) * 8);
            bv = *(const float4*)(bptr + (size_t)(s + 1) * 8 * KCB);
        }
#pragma unroll
        for (int kk = 0; kk < 8; kk++) {
            float a[8], b[8];
            *(float4*)&a[0] = *(const float4*)&As[cur][kk][ty * 8];
            *(float4*)&a[4] = *(const float4*)&As[cur][kk][ty * 8 + 4];
            *(float4*)&b[0] = *(const float4*)&Bs[cur][kk][tx * 8];
            *(float4*)&b[4] = *(const float4*)&Bs[cur][kk][tx * 8 + 4];
#pragma unroll
            for (int i = 0; i < 8; i++)
#pragma unroll
                for (int j = 0; j < 8; j++)
                    acc[i][j] = fmaf(a[i], b[j], acc[i][j]);
        }
        if (s < 31) {
            const int nxt = cur ^ 1;
            As[nxt][acol4 + 0][arow] = av.x;
            As[nxt][acol4 + 1][arow] = av.y;
            As[nxt][acol4 + 2][arow] = av.z;
            As[nxt][acol4 + 3][arow] = av.w;
            *(float4*)&Bs[nxt][brow][bcol] = bv;
            __syncthreads();
        }
    }

    // Epilogue: distance = (xnorm - 2*dot) + cnorm; per-thread row mins.
    float xn[8], cn[8];
#pragma unroll
    for (int i = 0; i < 8; i++) xn[i] = g_xnorm[r0 + ty * 8 + i];
#pragma unroll
    for (int j = 0; j < 8; j++) cn[j] = g_cnorm[c0 + tx * 8 + j];

#pragma unroll
    for (int i = 0; i < 8; i++) {
        float bvv = 1e30f;
        int   bii = 0;
#pragma unroll
        for (int j = 0; j < 8; j++) {
            // 2*dot is exact in fp32, so fma(-2,acc,xn) == (xn - 2*dot) rounding
            float sd = fmaf(-2.0f, acc[i][j], xn[i]) + cn[j];
            if (sd < bvv) { bvv = sd; bii = c0 + tx * 8 + j; }
        }
        redv[ty * 8 + i][tx] = bvv;
        redi[ty * 8 + i][tx] = bii;
    }
    __syncthreads();

    if (t < 128) {
        float bvv = redv[t][0];
        int   bii = redi[t][0];
#pragma unroll
        for (int x2 = 1; x2 < 16; x2++) {
            float v = redv[t][x2];
            if (v < bvv) { bvv = v; bii = redi[t][x2]; }  // ascending cols: first-min wins
        }
        g_pminval[(size_t)(r0 + t) * 8 + blockIdx.y] = bvv;
        g_pminidx[(size_t)(r0 + t) * 8 + blockIdx.y] = bii;
    }
}

// Combine 8 k-tile partials per row into the final argmin.
__global__ void k_combine() {
    int r = blockIdx.x * 1024 + threadIdx.x;   // grid 64
    const float* pv = &g_pminval[(size_t)r * 8];
    const int*   pi = &g_pminidx[(size_t)r * 8];
    float bv = pv[0];
    int   bi = pi[0];
#pragma unroll
    for (int j = 1; j < 8; j++) {
        float v = pv[j];
        if (v < bv) { bv = v; bi = pi[j]; }    // ascending tiles: first-min wins
    }
    g_idx[r] = bi;
}

// Per-row pass: ste output, loss sum, counts, dw accumulation.
// 8192 blocks x 256 threads; one warp per row.
__global__ void k_scatter(const float* __restrict__ x, float* __restrict__ out) {
    __shared__ float lsum[8];
    int warp = threadIdx.x >> 5, lane = threadIdx.x & 31;
    int r = blockIdx.x * 8 + warp;
    int k = g_idx[r];
    const float* xr = x + (size_t)r * DIM;
    const float* cr = g_cbT + (size_t)k * DIM;
    float* dw = g_dwT + (size_t)k * DIM;
    float ls = 0.0f;
#pragma unroll
    for (int i = 0; i < 8; i++) {
        int d = lane + 32 * i;
        float xv = xr[d];
        float q  = cr[d];
        float diff = q - xv;                    // matches stop_gradient(q - x)
        out[(size_t)r * DIM + d] = xv + diff;   // ste = x + (q - x), ref rounding
        ls = fmaf(diff, diff, ls);
        atomicAdd(&dw[d], xv);
    }
    if (lane == 0) atomicAdd(&g_counts[k], 1.0f);
#pragma unroll
    for (int o = 16; o; o >>= 1) ls += __shfl_xor_sync(0xffffffffu, ls, o);
    if (lane == 0) lsum[warp] = ls;
    __syncthreads();
    if (threadIdx.x == 0) {
        float s = 0.0f;
#pragma unroll
        for (int w = 0; w < 8; w++) s += lsum[w];
        atomicAdd(&g_loss_sum, s);
    }
}

// Small finalize: smoothed cluster sizes, bias, perplexity, loss scalars.
__global__ void k_finalize(const float* __restrict__ ema_cluster,
                           const int* __restrict__ counter,
                           float* __restrict__ out) {
    __shared__ float red[1024];
    __shared__ float nsh;
    int k = threadIdx.x;
    const float decay = 0.9f, one = 1.0f;
    float bias = one - powf(decay, (float)counter[0]);
    float cs  = g_counts[k];
    float hid = ema_cluster[k] * decay + cs * (one - decay);
    float avg_cs = hid / bias;

    red[k] = avg_cs;
    __syncthreads();
    for (int s2 = 512; s2 > 0; s2 >>= 1) {
        if (k < s2) red[k] += red[k + s2];
        __syncthreads();
    }
    if (k == 0) { nsh = red[0]; g_bias = bias; }
    __syncthreads();
    float n = nsh;
    g_smoothed[k] = (avg_cs + 1e-5f) / (n + 1024.0f * 1e-5f) * n;

    // perplexity
    float p = cs * (1.0f / 65536.0f);           // exact power-of-two scale
    float e = p * logf(p + 1e-10f);
    __syncthreads();
    red[k] = e;
    __syncthreads();
    for (int s2 = 512; s2 > 0; s2 >>= 1) {
        if (k < s2) red[k] += red[k + s2];
        __syncthreads();
    }
    if (k == 0) {
        out[OFF_PERP] = expf(-red[0]);
        out[OFF_LOSS] = 0.25f * (g_loss_sum * (1.0f / 16777216.0f)); // exact scales
    }
}

// new_codebook[d,k] = ((ema_dw*decay + dw*(1-decay))/bias) / smoothed[k]
__global__ void k_cbout(const float* __restrict__ ema_dw, float* __restrict__ out) {
    int d = blockIdx.x;    // 256
    int k = threadIdx.x;   // 1024
    const float decay = 0.9f, one = 1.0f;
    float hid = ema_dw[(size_t)d * KCB + k] * decay
              + g_dwT[(size_t)k * DIM + d] * (one - decay);
    float avg = hid / g_bias;
    out[OFF_CB + (size_t)d * KCB + k] = avg / g_smoothed[k];
}

// ---------------- launch -----------------------------------------------------
extern "C" void kernel_launch(void* const* d_in, const int* in_sizes, int n_in,
                              void* d_out, int out_size) {
    const float* x       = (const float*)d_in[0];  // inputs [64,32,32,256]
    const float* cb      = (const float*)d_in[1];  // codebook [256,1024]
    const float* ema_c   = (const float*)d_in[2];  // ema_hidden_cluster [1024]
    const float* ema_dw  = (const float*)d_in[3];  // ema_hidden_dw [256,1024]
    const int*   counter = (const int*)d_in[4];    // scalar int
    float* out = (float*)d_out;

    k_zero<<<1024, 256>>>();
    k_transpose<<<dim3(KCB / 32, DIM / 32), dim3(32, 32)>>>(cb);
    k_cnorm<<<KCB, 32>>>();
    k_xnorm<<<N_ROWS / 8, 256>>>(x);
    k_gemm_argmin<<<dim3(N_ROWS / 128, KCB / 128), 256>>>(x, cb);
    k_combine<<<N_ROWS / 1024, 1024>>>();
    k_scatter<<<N_ROWS / 8, 256>>>(x, out);
    k_finalize<<<1, 1024>>>(ema_c, counter, out);
    k_cbout<<<DIM, 1024>>>(ema_dw, out);
}